// round 1
// baseline (speedup 1.0000x reference)
#include <cuda_runtime.h>
#include <math.h>

// Problem constants (fixed dataset: support [25,2560] f32, query [4096,2560] f32,
// n_way=5, k_shot=5 -> out [4096,5] f32)
#define D      2560
#define NS     25
#define NQ     4096
#define NWAY   5
#define KSHOT  5
#define EPSV   1e-6f

#define KT            256   // K-tile staged in smem
#define ROWS_PER_CTA  32    // 8 warps x TM rows
#define TM            4     // query rows per warp (register tile)
#define THREADS       256

// ||support_row + eps||^2, computed once by prep kernel
__device__ float g_snorm[NS];

// ---------------------------------------------------------------------------
// Prep: per-support-row squared norm of (s + eps). 25 blocks x 256 threads.
// ---------------------------------------------------------------------------
__global__ void prep_snorm_kernel(const float* __restrict__ support) {
    const int s = blockIdx.x;
    const float* row = support + (size_t)s * D;
    float acc = 0.f;
    for (int idx = threadIdx.x; idx < D / 4; idx += blockDim.x) {
        float4 v = *reinterpret_cast<const float4*>(row + idx * 4);
        float x = v.x + EPSV, y = v.y + EPSV, z = v.z + EPSV, w = v.w + EPSV;
        acc = fmaf(x, x, acc);
        acc = fmaf(y, y, acc);
        acc = fmaf(z, z, acc);
        acc = fmaf(w, w, acc);
    }
    // warp reduce
    #pragma unroll
    for (int off = 16; off > 0; off >>= 1)
        acc += __shfl_xor_sync(0xffffffffu, acc, off);
    __shared__ float ws[8];
    const int warp = threadIdx.x >> 5;
    const int lane = threadIdx.x & 31;
    if (lane == 0) ws[warp] = acc;
    __syncthreads();
    if (threadIdx.x == 0) {
        float t = 0.f;
        #pragma unroll
        for (int i = 0; i < 8; ++i) t += ws[i];
        g_snorm[s] = t;
    }
}

// ---------------------------------------------------------------------------
// Main: dot-product formulation.
//   dist^2[q][s] = ||q||^2 + ||s+eps||^2 - 2 * dot(q, s+eps)
// Each CTA: 32 query rows, 8 warps, warp owns TM=4 rows.
// Support staged in smem per K-tile (+eps applied during staging).
// Each lane accumulates acc[4][25] over its column subset; butterfly-reduce
// across lanes at the end; lane 0 writes the 5 way-scores per row.
// ---------------------------------------------------------------------------
__global__ __launch_bounds__(THREADS)
void pairdist_main_kernel(const float* __restrict__ support,
                          const float* __restrict__ query,
                          float* __restrict__ out) {
    __shared__ float sS[NS][KT];

    const int tid  = threadIdx.x;
    const int warp = tid >> 5;
    const int ln   = tid & 31;
    const int row0 = blockIdx.x * ROWS_PER_CTA + warp * TM;

    float acc[TM][NS];
    #pragma unroll
    for (int m = 0; m < TM; ++m)
        #pragma unroll
        for (int s = 0; s < NS; ++s)
            acc[m][s] = 0.f;
    float qn[TM];
    #pragma unroll
    for (int m = 0; m < TM; ++m) qn[m] = 0.f;

    for (int k0 = 0; k0 < D; k0 += KT) {
        __syncthreads();  // previous tile fully consumed
        // stage support tile (+eps), coalesced float4
        for (int i = tid; i < NS * (KT / 4); i += THREADS) {
            const int s  = i / (KT / 4);
            const int c4 = (i - s * (KT / 4)) * 4;
            float4 v = *reinterpret_cast<const float4*>(support + (size_t)s * D + k0 + c4);
            v.x += EPSV; v.y += EPSV; v.z += EPSV; v.w += EPSV;
            *reinterpret_cast<float4*>(&sS[s][c4]) = v;
        }
        __syncthreads();

        #pragma unroll
        for (int g = 0; g < KT / 128; ++g) {
            const int cl = g * 128 + ln * 4;
            float4 qv[TM];
            #pragma unroll
            for (int m = 0; m < TM; ++m)
                qv[m] = *reinterpret_cast<const float4*>(
                    query + (size_t)(row0 + m) * D + k0 + cl);
            #pragma unroll
            for (int m = 0; m < TM; ++m) {
                qn[m] = fmaf(qv[m].x, qv[m].x, qn[m]);
                qn[m] = fmaf(qv[m].y, qv[m].y, qn[m]);
                qn[m] = fmaf(qv[m].z, qv[m].z, qn[m]);
                qn[m] = fmaf(qv[m].w, qv[m].w, qn[m]);
            }
            #pragma unroll
            for (int s = 0; s < NS; ++s) {
                const float4 sv = *reinterpret_cast<const float4*>(&sS[s][cl]);
                #pragma unroll
                for (int m = 0; m < TM; ++m) {
                    float a = acc[m][s];
                    a = fmaf(qv[m].x, sv.x, a);
                    a = fmaf(qv[m].y, sv.y, a);
                    a = fmaf(qv[m].z, sv.z, a);
                    a = fmaf(qv[m].w, sv.w, a);
                    acc[m][s] = a;
                }
            }
        }
    }

    // butterfly reduce each accumulator across the 32 lanes (result in all lanes)
    #pragma unroll
    for (int m = 0; m < TM; ++m) {
        #pragma unroll
        for (int s = 0; s < NS; ++s) {
            float v = acc[m][s];
            v += __shfl_xor_sync(0xffffffffu, v, 16);
            v += __shfl_xor_sync(0xffffffffu, v, 8);
            v += __shfl_xor_sync(0xffffffffu, v, 4);
            v += __shfl_xor_sync(0xffffffffu, v, 2);
            v += __shfl_xor_sync(0xffffffffu, v, 1);
            acc[m][s] = v;
        }
        float v = qn[m];
        v += __shfl_xor_sync(0xffffffffu, v, 16);
        v += __shfl_xor_sync(0xffffffffu, v, 8);
        v += __shfl_xor_sync(0xffffffffu, v, 4);
        v += __shfl_xor_sync(0xffffffffu, v, 2);
        v += __shfl_xor_sync(0xffffffffu, v, 1);
        qn[m] = v;
    }

    // epilogue: dist = sqrt(qn + snorm - 2*dot); score[w] = -sum_k dist
    // (all indices compile-time constant -> no register spill; lane 0 writes)
    if (ln == 0) {
        #pragma unroll
        for (int m = 0; m < TM; ++m) {
            float way[NWAY];
            #pragma unroll
            for (int w = 0; w < NWAY; ++w) {
                float sum = 0.f;
                #pragma unroll
                for (int k = 0; k < KSHOT; ++k) {
                    const int s = w * KSHOT + k;
                    float d2 = qn[m] + g_snorm[s] - 2.f * acc[m][s];
                    sum += sqrtf(fmaxf(d2, 0.f));
                }
                way[w] = -sum;
            }
            float* orow = out + (size_t)(row0 + m) * NWAY;
            #pragma unroll
            for (int w = 0; w < NWAY; ++w) orow[w] = way[w];
        }
    }
}

// ---------------------------------------------------------------------------
extern "C" void kernel_launch(void* const* d_in, const int* in_sizes, int n_in,
                              void* d_out, int out_size) {
    const float* support = (const float*)d_in[0];
    const float* query   = (const float*)d_in[1];
    // defensive: support is the smaller tensor (25*2560 vs 4096*2560)
    if (n_in >= 2 && in_sizes[0] > in_sizes[1]) {
        const float* t = support; support = query; query = t;
    }
    float* out = (float*)d_out;

    prep_snorm_kernel<<<NS, 256>>>(support);
    pairdist_main_kernel<<<NQ / ROWS_PER_CTA, THREADS>>>(support, query, out);
}